// round 10
// baseline (speedup 1.0000x reference)
#include <cuda_runtime.h>
#include <cuda_bf16.h>
#include <cstdint>

namespace {
constexpr int Bn = 32;
constexpr int Tn = 1024;
constexpr int M  = Bn * 1024;

constexpr int Lc = 16;
constexpr int Cc = Tn / Lc;         // 64

constexpr int SZ  = 512 * 512;      // fp32 elements per matrix
constexpr int SZW = 256 * 512;      // packed bf16x2 words per matrix

// fragment-major staging: per buffer = A-hi 2048 | A-lo 2048 | B 2048 words
constexpr int BUFW = 6144;
constexpr int SMEM_BYTES = 2 * BUFW * 4;   // 49152
}

// ---------------------------------------------------------------------------
// Static device scratch
// ---------------------------------------------------------------------------
__device__ float    g_Rf[16 * SZ];      // R^1..R^16 fp32
__device__ uint32_t g_Rh[16 * SZW];     // packed bf16 hi of R^1..R^16
__device__ uint32_t g_Rl[16 * SZW];
__device__ float    g_Sf[5 * SZ];       // S^2,S^4,S^8,S^16,S^32 (S = R^16)
__device__ uint32_t g_Sh[5 * SZW];
__device__ uint32_t g_Sl[5 * SZW];
__device__ uint32_t g_Wh[SZW];
__device__ uint32_t g_Wl[SZW];
__device__ float    g_V0[Cc * Bn * 512];
__device__ float    g_V1[Cc * Bn * 512];

// ---------------------------------------------------------------------------
// helpers
// ---------------------------------------------------------------------------
__device__ __forceinline__ uint32_t packbf(float a, float b) {
    uint32_t r;  // low half = a, high half = b
    asm("cvt.rn.bf16x2.f32 %0, %1, %2;" : "=r"(r) : "f"(b), "f"(a));
    return r;
}
__device__ __forceinline__ float lo_f(uint32_t p) { return __uint_as_float(p << 16); }
__device__ __forceinline__ float hi_f(uint32_t p) { return __uint_as_float(p & 0xFFFF0000u); }

__device__ __forceinline__ void mma16816(float* c, const uint32_t* a,
                                         uint32_t b0, uint32_t b1) {
    asm volatile(
        "mma.sync.aligned.m16n8k16.row.col.f32.bf16.bf16.f32 "
        "{%0,%1,%2,%3}, {%4,%5,%6,%7}, {%8,%9}, {%0,%1,%2,%3};"
        : "+f"(c[0]), "+f"(c[1]), "+f"(c[2]), "+f"(c[3])
        : "r"(a[0]), "r"(a[1]), "r"(a[2]), "r"(a[3]), "r"(b0), "r"(b1));
}

// ---------------------------------------------------------------------------
// HMMA core, fragment-major staging.
//   acc[2][4][4] += A(128x512 fp32, converted in-kernel) @ B(bf16 hi/lo packed)
// 256 threads, warps 4x2 -> 32x32 per warp. K chunked by 32 (16 chunks).
// arow: thread A ptr (row = tid>>1, k-offset (tid&1)*16)
// bh/bl: packed B global base + bn; word (w, n) at w*512 + n.
//
// Staging layout per buffer (words):
//   A-hi [0,2048):   s*1024 + mf*128 + (g*4+qi)*4 + (khalf*2 + rowpair)
//   A-lo [2048,4096): same + 2048
//   B    [4096,6144): s*1024 + nf*128 + (g*4+qi)*4 + (khalf*2 + hilo)
// Producer stores use diagonal schedules -> conflict-free.
// Consumer fragment loads are single LDS.128 per fragment.
// ---------------------------------------------------------------------------
__device__ __forceinline__ void hmma_core_bb(const float* __restrict__ arow,
                                             const uint32_t* __restrict__ bh,
                                             const uint32_t* __restrict__ bl,
                                             float acc[2][4][4])
{
    extern __shared__ uint32_t sw[];
    const int tid  = threadIdx.x;
    const int lane = tid & 31, wid = tid >> 5;
    const int mo16 = (wid >> 1) * 2;       // A frag base (m16 units)
    const int no8  = (wid & 1) * 4;        // B frag base (n8 units)

    // A producer indices (thread t -> row t>>1, k-half t&1)
    const int pr  = tid >> 1;
    const int ps  = tid & 1;
    const int pmf = pr >> 4;
    const int pg  = pr & 7;
    const int prp = (pr >> 3) & 1;
    const int pdv = pg + (pg >> 2) + 4 * ps;   // A store diagonal

    // B producer indices (thread t -> khalf t&1, s (t>>1)&1, n t>>2)
    const int bkh = tid & 1;
    const int bs  = (tid >> 1) & 1;
    const int bnl = tid >> 2;              // 0..63
    const int bg  = bnl & 7;
    const int bnf = bnl >> 3;
    const int bdv = bg + (bg >> 2) + 2 * bs;   // B store diagonal
    const int bwb = bs * 8 + bkh * 4;          // B word base within chunk

    float af[16];
    uint32_t bhw[4], blw[4];

    auto LOAD = [&](int kc) {
        const float* ap = arow + kc * 32;
        float4 v;
        v = *(const float4*)(ap + 0);  af[0] = v.x;  af[1] = v.y;  af[2] = v.z;  af[3] = v.w;
        v = *(const float4*)(ap + 4);  af[4] = v.x;  af[5] = v.y;  af[6] = v.z;  af[7] = v.w;
        v = *(const float4*)(ap + 8);  af[8] = v.x;  af[9] = v.y;  af[10] = v.z; af[11] = v.w;
        v = *(const float4*)(ap + 12); af[12] = v.x; af[13] = v.y; af[14] = v.z; af[15] = v.w;
        const int off = (kc * 16 + bwb) * 512 + bnl;
#pragma unroll
        for (int q = 0; q < 4; q++) {
            bhw[q] = bh[off + q * 512];
            blw[q] = bl[off + q * 512];
        }
    };

    auto STORE = [&](int bi) {
        uint32_t h[8], l[8];
#pragma unroll
        for (int j = 0; j < 8; j++) {
            h[j] = packbf(af[2 * j], af[2 * j + 1]);
            l[j] = packbf(af[2 * j] - lo_f(h[j]), af[2 * j + 1] - hi_f(h[j]));
        }
        const int abase = bi * BUFW + ps * 1024 + pmf * 128;
#pragma unroll
        for (int i = 0; i < 8; i++) {
            const int j  = (i + pdv) & 7;
            const int q  = j & 3;
            const int kh = j >> 2;
            const int addr = abase + (pg * 4 + q) * 4 + kh * 2 + prp;
            sw[addr]        = h[j];
            sw[addr + 2048] = l[j];
        }
        const int bbase = bi * BUFW + 4096 + bs * 1024 + bnf * 128;
#pragma unroll
        for (int i = 0; i < 4; i++) {
            const int q = (i + bdv) & 3;
            *(uint2*)&sw[bbase + (bg * 4 + q) * 4 + bkh * 2] = make_uint2(bhw[q], blw[q]);
        }
    };

    auto COMPUTE = [&](int bi) {
        const int base = bi * BUFW;
#pragma unroll
        for (int s = 0; s < 2; s++) {
            uint4 AH[2], AL[2];
#pragma unroll
            for (int mf = 0; mf < 2; mf++) {
                const int fa = base + s * 1024 + (mo16 + mf) * 128 + lane * 4;
                AH[mf] = *(const uint4*)&sw[fa];
                AL[mf] = *(const uint4*)&sw[fa + 2048];
            }
#pragma unroll
            for (int f = 0; f < 4; f++) {
                const uint4 B4 = *(const uint4*)&sw[base + 4096 + s * 1024 +
                                                   (no8 + f) * 128 + lane * 4];
                // B4 = {bh0, bl0, bh1, bl1}
#pragma unroll
                for (int mf = 0; mf < 2; mf++) {
                    mma16816(acc[mf][f], (const uint32_t*)&AH[mf], B4.x, B4.z);
                    mma16816(acc[mf][f], (const uint32_t*)&AH[mf], B4.y, B4.w);
                    mma16816(acc[mf][f], (const uint32_t*)&AL[mf], B4.x, B4.z);
                }
            }
        }
    };

    LOAD(0);
    STORE(0);
    __syncthreads();
    int cur = 0;
    for (int kc = 0; kc < 16; kc++) {
        if (kc < 15) LOAD(kc + 1);
        COMPUTE(cur);
        if (kc < 15) {
            STORE(cur ^ 1);
            __syncthreads();
            cur ^= 1;
        }
    }
}

// ---------------------------------------------------------------------------
// generic C = A @ B (fp32 out).  grid (n/64, m/128).  Used for XW.
// ---------------------------------------------------------------------------
__global__ __launch_bounds__(256, 2) void hmma_gemm_bb(
    const float* __restrict__ A, const uint32_t* __restrict__ Bh,
    const uint32_t* __restrict__ Bl, float* __restrict__ C)
{
    const int bn = blockIdx.x * 64;
    const int bm = blockIdx.y * 128;
    const int tid = threadIdx.x;
    const float* arow = A + (size_t)(bm + (tid >> 1)) * 512 + (tid & 1) * 16;
    float acc[2][4][4] = {};
    hmma_core_bb(arow, Bh + bn, Bl + bn, acc);

    const int lane = tid & 31, wid = tid >> 5;
    const int g = lane >> 2, qi = lane & 3;
    const int mo = (wid >> 1) * 32, no = (wid & 1) * 32;
#pragma unroll
    for (int mf = 0; mf < 2; mf++)
#pragma unroll
        for (int f = 0; f < 4; f++) {
            const int r0  = bm + mo + mf * 16 + g;
            const int col = bn + no + f * 8 + 2 * qi;
            *(float2*)(C + (size_t)r0 * 512 + col) =
                make_float2(acc[mf][f][0], acc[mf][f][1]);
            *(float2*)(C + (size_t)(r0 + 8) * 512 + col) =
                make_float2(acc[mf][f][2], acc[mf][f][3]);
        }
}

// ---------------------------------------------------------------------------
// Mega pass1 step: y < 16 -> pass1 tile; y >= 16 -> ladder tile.
// Ladder blocks emit fp32 C and packed bf16 hi/lo (shuffle epilogue).
// t==15 pass1 blocks also seed V0.
// ---------------------------------------------------------------------------
__global__ __launch_bounds__(256, 2) void mega_step_kernel(
    const uint32_t* __restrict__ Rh, const uint32_t* __restrict__ Rl,
    float* __restrict__ O, int t, float* __restrict__ V0,
    const float* __restrict__ LA,
    const uint32_t* __restrict__ LBh, const uint32_t* __restrict__ LBl,
    float* __restrict__ LCf, uint32_t* __restrict__ LCh, uint32_t* __restrict__ LCl)
{
    const int bn  = blockIdx.x * 64;
    const int tid = threadIdx.x;
    const int lane = tid & 31, wid = tid >> 5;
    const int g = lane >> 2, qi = lane & 3;
    const int mo = (wid >> 1) * 32, no = (wid & 1) * 32;

    if (blockIdx.y < 16) {
        const int bm = blockIdx.y * 128;
        const int srow = bm + (tid >> 1);
        const float* arow = O + ((size_t)(srow & 31) * Tn + (size_t)(srow >> 5) * Lc + (t - 1)) * 512
                            + (tid & 1) * 16;
        float acc[2][4][4] = {};
        hmma_core_bb(arow, Rh + bn, Rl + bn, acc);

#pragma unroll
        for (int mf = 0; mf < 2; mf++)
#pragma unroll
            for (int f = 0; f < 4; f++) {
                const int col = bn + no + f * 8 + 2 * qi;
#pragma unroll
                for (int h = 0; h < 2; h++) {
                    const int r = bm + mo + mf * 16 + g + h * 8;
                    float* op = O + ((size_t)(r & 31) * Tn + (size_t)(r >> 5) * Lc + t) * 512 + col;
                    float2 e = *(float2*)op;
                    e.x += acc[mf][f][2 * h];
                    e.y += acc[mf][f][2 * h + 1];
                    *(float2*)op = e;
                    if (t == Lc - 1)
                        *(float2*)(V0 + (size_t)r * 512 + col) = e;
                }
            }
    } else {
        const int y2 = blockIdx.y - 16;
        const int z  = y2 >> 2;
        const int mrow = (y2 & 3) * 128;
        const float* arow = LA + (size_t)z * SZ + (size_t)(mrow + (tid >> 1)) * 512 + (tid & 1) * 16;
        float acc[2][4][4] = {};
        hmma_core_bb(arow, LBh + bn, LBl + bn, acc);

        float* Cz = LCf + (size_t)z * SZ;
        uint32_t* Dh = LCh + (size_t)z * SZW;
        uint32_t* Dl = LCl + (size_t)z * SZW;
#pragma unroll
        for (int mf = 0; mf < 2; mf++)
#pragma unroll
            for (int f = 0; f < 4; f++) {
                const int r0  = mrow + mo + mf * 16 + g;
                const int col = bn + no + f * 8 + 2 * qi;
                *(float2*)(Cz + (size_t)r0 * 512 + col) =
                    make_float2(acc[mf][f][0], acc[mf][f][1]);
                *(float2*)(Cz + (size_t)(r0 + 8) * 512 + col) =
                    make_float2(acc[mf][f][2], acc[mf][f][3]);

                float pc0 = __shfl_sync(0xffffffffu, acc[mf][f][0], (lane + 4) & 31);
                float pc1 = __shfl_sync(0xffffffffu, acc[mf][f][1], (lane + 4) & 31);
                float pc2 = __shfl_sync(0xffffffffu, acc[mf][f][2], (lane + 4) & 31);
                float pc3 = __shfl_sync(0xffffffffu, acc[mf][f][3], (lane + 4) & 31);
                if ((g & 1) == 0) {
                    const int w0 = r0 >> 1;
                    const int w1 = (r0 + 8) >> 1;
                    uint32_t h0 = packbf(acc[mf][f][0], pc0);
                    Dh[(size_t)w0 * 512 + col] = h0;
                    Dl[(size_t)w0 * 512 + col] =
                        packbf(acc[mf][f][0] - lo_f(h0), pc0 - hi_f(h0));
                    uint32_t h1 = packbf(acc[mf][f][1], pc1);
                    Dh[(size_t)w0 * 512 + col + 1] = h1;
                    Dl[(size_t)w0 * 512 + col + 1] =
                        packbf(acc[mf][f][1] - lo_f(h1), pc1 - hi_f(h1));
                    uint32_t h2 = packbf(acc[mf][f][2], pc2);
                    Dh[(size_t)w1 * 512 + col] = h2;
                    Dl[(size_t)w1 * 512 + col] =
                        packbf(acc[mf][f][2] - lo_f(h2), pc2 - hi_f(h2));
                    uint32_t h3 = packbf(acc[mf][f][3], pc3);
                    Dh[(size_t)w1 * 512 + col + 1] = h3;
                    Dl[(size_t)w1 * 512 + col + 1] =
                        packbf(acc[mf][f][3] - lo_f(h3), pc3 - hi_f(h3));
                }
            }
    }
}

// ---------------------------------------------------------------------------
// Hillis-Steele scan step: Vout[c] = Vin[c] + (c>=d ? Vin[c-d] @ S^d : 0)
// ---------------------------------------------------------------------------
__global__ __launch_bounds__(256, 2) void hmma_scan_step(
    float* __restrict__ Vout, const float* __restrict__ Vin,
    const uint32_t* __restrict__ Sh, const uint32_t* __restrict__ Sl, int d)
{
    const int bn = blockIdx.x * 64;
    const int bm = blockIdx.y * 128;
    const int tid = threadIdx.x;
    const int srow = bm + (tid >> 1);
    const int csrc = (srow >> 5) - d;
    const int asrc = (csrc >= 0) ? (csrc * 32 + (srow & 31)) : srow;
    const float* arow = Vin + (size_t)asrc * 512 + (tid & 1) * 16;
    float acc[2][4][4] = {};
    hmma_core_bb(arow, Sh + bn, Sl + bn, acc);

    const int lane = tid & 31, wid = tid >> 5;
    const int g = lane >> 2, qi = lane & 3;
    const int mo = (wid >> 1) * 32, no = (wid & 1) * 32;
#pragma unroll
    for (int mf = 0; mf < 2; mf++)
#pragma unroll
        for (int f = 0; f < 4; f++) {
            const int col = bn + no + f * 8 + 2 * qi;
#pragma unroll
            for (int h = 0; h < 2; h++) {
                const int r = bm + mo + mf * 16 + g + h * 8;
                float2 e = *(const float2*)(Vin + (size_t)r * 512 + col);
                if ((r >> 5) >= d) {
                    e.x += acc[mf][f][2 * h];
                    e.y += acc[mf][f][2 * h + 1];
                }
                *(float2*)(Vout + (size_t)r * 512 + col) = e;
            }
        }
}

// ---------------------------------------------------------------------------
// pass3: O[b, 16*(c+1)+t, :] += V[c] @ R^{t+1}.  grid (8, 16, 16: t)
// ---------------------------------------------------------------------------
__global__ __launch_bounds__(256, 2) void hmma_pass3_bb(
    float* __restrict__ O, const float* __restrict__ V,
    const uint32_t* __restrict__ Rh, const uint32_t* __restrict__ Rl)
{
    const int t  = blockIdx.z;
    const int bn = blockIdx.x * 64;
    const int bm = blockIdx.y * 128;
    const int tid = threadIdx.x;
    const float* arow = V + (size_t)(bm + (tid >> 1)) * 512 + (tid & 1) * 16;
    float acc[2][4][4] = {};
    hmma_core_bb(arow, Rh + (size_t)t * SZW + bn, Rl + (size_t)t * SZW + bn, acc);

    const int lane = tid & 31, wid = tid >> 5;
    const int g = lane >> 2, qi = lane & 3;
    const int mo = (wid >> 1) * 32, no = (wid & 1) * 32;
#pragma unroll
    for (int mf = 0; mf < 2; mf++)
#pragma unroll
        for (int f = 0; f < 4; f++) {
            const int col = bn + no + f * 8 + 2 * qi;
#pragma unroll
            for (int h = 0; h < 2; h++) {
                const int r = bm + mo + mf * 16 + g + h * 8;
                const int cidx = r >> 5;       // = c-1
                if (cidx < Cc - 1) {
                    const int b = r & 31;
                    float* op = O + ((size_t)b * Tn + (size_t)(cidx + 1) * Lc + t) * 512 + col;
                    float2 e = *(float2*)op;
                    e.x += acc[mf][f][2 * h];
                    e.y += acc[mf][f][2 * h + 1];
                    *(float2*)op = e;
                }
            }
        }
}

// ---------------------------------------------------------------------------
// utilities
// ---------------------------------------------------------------------------
__global__ void pack_kernel(const float* __restrict__ src,
                            uint32_t* __restrict__ dh, uint32_t* __restrict__ dl,
                            int total)
{
    const int i = blockIdx.x * 256 + threadIdx.x;
    if (i >= total) return;
    const int w = i >> 9, n = i & 511;
    const float* s = src + (size_t)(2 * w) * 512 + n;
    const float s0 = s[0], s1 = s[512];
    const uint32_t h = packbf(s0, s1);
    dh[i] = h;
    dl[i] = packbf(s0 - lo_f(h), s1 - hi_f(h));
}

__global__ void copy_floats_kernel(float* __restrict__ dst,
                                   const float* __restrict__ src, int n4)
{
    int i = blockIdx.x * blockDim.x + threadIdx.x;
    if (i < n4) ((float4*)dst)[i] = ((const float4*)src)[i];
}

// ---------------------------------------------------------------------------
// Launch sequence
// ---------------------------------------------------------------------------
extern "C" void kernel_launch(void* const* d_in, const int* in_sizes, int n_in,
                              void* d_out, int out_size)
{
    const float* x = (const float*)d_in[0];
    const float* w = (const float*)d_in[1];
    const float* r = (const float*)d_in[2];
    float* o = (float*)d_out;
    (void)in_sizes; (void)n_in; (void)out_size;

    float *Rf, *Sf, *V0, *V1;
    uint32_t *Rh, *Rl, *Sh, *Sl, *Wh, *Wl;
    cudaGetSymbolAddress((void**)&Rf, g_Rf);
    cudaGetSymbolAddress((void**)&Rh, g_Rh);
    cudaGetSymbolAddress((void**)&Rl, g_Rl);
    cudaGetSymbolAddress((void**)&Sf, g_Sf);
    cudaGetSymbolAddress((void**)&Sh, g_Sh);
    cudaGetSymbolAddress((void**)&Sl, g_Sl);
    cudaGetSymbolAddress((void**)&Wh, g_Wh);
    cudaGetSymbolAddress((void**)&Wl, g_Wl);
    cudaGetSymbolAddress((void**)&V0, g_V0);
    cudaGetSymbolAddress((void**)&V1, g_V1);

    cudaFuncSetAttribute(hmma_gemm_bb,    cudaFuncAttributeMaxDynamicSharedMemorySize, SMEM_BYTES);
    cudaFuncSetAttribute(mega_step_kernel, cudaFuncAttributeMaxDynamicSharedMemorySize, SMEM_BYTES);
    cudaFuncSetAttribute(hmma_scan_step,  cudaFuncAttributeMaxDynamicSharedMemorySize, SMEM_BYTES);
    cudaFuncSetAttribute(hmma_pass3_bb,   cudaFuncAttributeMaxDynamicSharedMemorySize, SMEM_BYTES);

    // Prologue: pack W and R, seed Rf slot 0 with R^1.
    pack_kernel<<<SZW / 256, 256>>>(w, Wh, Wl, SZW);
    pack_kernel<<<SZW / 256, 256>>>(r, Rh, Rl, SZW);
    copy_floats_kernel<<<SZ / 4 / 256, 256>>>(Rf, r, SZ / 4);

    // Phase A: O = X @ W
    hmma_gemm_bb<<<dim3(8, M / 128), 256, SMEM_BYTES>>>(x, Wh, Wl, o);

    // Phase C + B: pass1 steps with ladder piggyback.
    struct Lad { const float* A; const uint32_t *Bh, *Bl; float* Cf; uint32_t *Ch, *Cl; int mt; };
    Lad lad[16];
    for (int t = 0; t < 16; t++) lad[t] = {o, Rh, Rl, Rf, Rh, Rl, 0};
    lad[1]  = {r,            Rh,            Rl,            Rf + (size_t)1 * SZ,  Rh + (size_t)1 * SZW,  Rl + (size_t)1 * SZW,  4};   // R^2
    lad[2]  = {Rf,           Rh + 1 * SZW,  Rl + 1 * SZW,  Rf + (size_t)2 * SZ,  Rh + (size_t)2 * SZW,  Rl + (size_t)2 * SZW,  8};   // R^3,R^4
    lad[3]  = {Rf,           Rh + 3 * SZW,  Rl + 3 * SZW,  Rf + (size_t)4 * SZ,  Rh + (size_t)4 * SZW,  Rl + (size_t)4 * SZW,  16};  // R^5..R^8
    lad[4]  = {Rf,           Rh + 7 * SZW,  Rl + 7 * SZW,  Rf + (size_t)8 * SZ,  Rh + (size_t)8 * SZW,  Rl + (size_t)8 * SZW,  32};  // R^9..R^16
    lad[5]  = {Rf + 15 * SZ, Rh + 15 * SZW, Rl + 15 * SZW, Sf,                   Sh,                    Sl,                    4};   // S^2
    lad[6]  = {Sf,           Sh,            Sl,            Sf + (size_t)1 * SZ,  Sh + (size_t)1 * SZW,  Sl + (size_t)1 * SZW,  4};   // S^4
    lad[7]  = {Sf + 1 * SZ,  Sh + 1 * SZW,  Sl + 1 * SZW,  Sf + (size_t)2 * SZ,  Sh + (size_t)2 * SZW,  Sl + (size_t)2 * SZW,  4};   // S^8
    lad[8]  = {Sf + 2 * SZ,  Sh + 2 * SZW,  Sl + 2 * SZW,  Sf + (size_t)3 * SZ,  Sh + (size_t)3 * SZW,  Sl + (size_t)3 * SZW,  4};   // S^16
    lad[9]  = {Sf + 3 * SZ,  Sh + 3 * SZW,  Sl + 3 * SZW,  Sf + (size_t)4 * SZ,  Sh + (size_t)4 * SZW,  Sl + (size_t)4 * SZW,  4};   // S^32

    for (int t = 1; t < Lc; t++) {
        const Lad& L = lad[t];
        mega_step_kernel<<<dim3(8, 16 + L.mt), 256, SMEM_BYTES>>>(
            Rh, Rl, o, t, V0, L.A, L.Bh, L.Bl, L.Cf, L.Ch, L.Cl);
    }

    // Phase D: carry scan (Hillis-Steele over 64 chunk states)
    const float* vin = V0;
    float* vout = V1;
    for (int i = 0; i < 6; i++) {
        const int d = 1 << i;
        const uint32_t* Sph = (i == 0) ? (Rh + (size_t)15 * SZW) : (Sh + (size_t)(i - 1) * SZW);
        const uint32_t* Spl = (i == 0) ? (Rl + (size_t)15 * SZW) : (Sl + (size_t)(i - 1) * SZW);
        hmma_scan_step<<<dim3(8, 16), 256, SMEM_BYTES>>>(vout, vin, Sph, Spl, d);
        const float* tmp = vin; vin = vout; vout = (float*)tmp;
    }

    // Phase E: batched correction
    hmma_pass3_bb<<<dim3(8, 16, 16), 256, SMEM_BYTES>>>(o, vin, Rh, Rl);
}

// round 11
// speedup vs baseline: 1.3765x; 1.3765x over previous
#include <cuda_runtime.h>
#include <cuda_bf16.h>
#include <cstdint>

namespace {
constexpr int Bn = 32;
constexpr int Tn = 1024;
constexpr int M  = Bn * 1024;

constexpr int Lc = 16;
constexpr int Cc = Tn / Lc;         // 64

constexpr int SZ  = 512 * 512;      // fp32 elements per matrix
constexpr int SZW = 256 * 512;      // packed bf16x2 words per matrix
constexpr int WST = 20;             // smem row stride in words (80B: ldmatrix conflict-free)
constexpr int BUFW = 7680;          // words per stage buffer (Ah 2560 | Al 2560 | Bh 1280 | Bl 1280)
constexpr int SMEM_BYTES = 2 * BUFW * 4;   // 61440
}

// ---------------------------------------------------------------------------
// Static device scratch
// ---------------------------------------------------------------------------
__device__ float    g_Rf[16 * SZ];      // R^1..R^16 fp32
__device__ uint32_t g_Rh[16 * SZW];     // packed bf16 hi of R^1..R^16
__device__ uint32_t g_Rl[16 * SZW];
__device__ float    g_Sf[5 * SZ];       // S^2,S^4,S^8,S^16,S^32 (S = R^16)
__device__ uint32_t g_Sh[5 * SZW];
__device__ uint32_t g_Sl[5 * SZW];
__device__ uint32_t g_Wh[SZW];
__device__ uint32_t g_Wl[SZW];
__device__ float    g_V0[Cc * Bn * 512];
__device__ float    g_V1[Cc * Bn * 512];

// ---------------------------------------------------------------------------
// helpers
// ---------------------------------------------------------------------------
__device__ __forceinline__ uint32_t packbf(float a, float b) {
    uint32_t r;  // low half = a, high half = b
    asm("cvt.rn.bf16x2.f32 %0, %1, %2;" : "=r"(r) : "f"(b), "f"(a));
    return r;
}
__device__ __forceinline__ float lo_f(uint32_t p) { return __uint_as_float(p << 16); }
__device__ __forceinline__ float hi_f(uint32_t p) { return __uint_as_float(p & 0xFFFF0000u); }

__device__ __forceinline__ void mma16816(float* c, const uint32_t* a,
                                         uint32_t b0, uint32_t b1) {
    asm volatile(
        "mma.sync.aligned.m16n8k16.row.col.f32.bf16.bf16.f32 "
        "{%0,%1,%2,%3}, {%4,%5,%6,%7}, {%8,%9}, {%0,%1,%2,%3};"
        : "+f"(c[0]), "+f"(c[1]), "+f"(c[2]), "+f"(c[3])
        : "r"(a[0]), "r"(a[1]), "r"(a[2]), "r"(a[3]), "r"(b0), "r"(b1));
}

__device__ __forceinline__ void ldsm4(uint32_t& r0, uint32_t& r1,
                                      uint32_t& r2, uint32_t& r3, uint32_t addr) {
    asm volatile(
        "ldmatrix.sync.aligned.m8n8.x4.shared.b16 {%0,%1,%2,%3}, [%4];"
        : "=r"(r0), "=r"(r1), "=r"(r2), "=r"(r3) : "r"(addr));
}

// ---------------------------------------------------------------------------
// Double-buffered HMMA core (round-9 layout; ldmatrix fragment loads).
//   acc[2][4][4] += A(128x512 fp32, converted in-kernel) @ B(packed bf16 hi/lo)
// 256 threads, warps 4x2 -> 32x32 per warp. K chunked by 32 (16 chunks).
// arow: thread A ptr (row = tid>>1, k-offset (tid&1)*16)
// bh/bl: packed B global base (incl. bn + (tid&63)); word (w,n) at w*512.
// Staging (words/buffer): Ah rows[128]xWST | Al +2560 | Bh +5120 rows[64]xWST | Bl +6400.
// ---------------------------------------------------------------------------
__device__ __forceinline__ void hmma_core_bb(const float* __restrict__ arow,
                                             const uint32_t* __restrict__ bh,
                                             const uint32_t* __restrict__ bl,
                                             float acc[2][4][4])
{
    extern __shared__ uint32_t sw[];
    const uint32_t sb = (uint32_t)__cvta_generic_to_shared(sw);
    const int tid  = threadIdx.x;
    const int lane = tid & 31, wid = tid >> 5;
    const int mo = (wid >> 1) * 32, no = (wid & 1) * 32;

    const int sar = tid >> 1;          // A staging row
    const int saw = (tid & 1) * 8;     // A word base (0 / 8)
    const int sbw = (tid >> 6) * 4;    // B word base (0,4,8,12)

    // ldmatrix per-lane address components (in words)
    const int aoffw = (lane & 15) * WST + (lane >> 4) * 4;               // A lanes
    const int jj = lane >> 3, iL = lane & 7;
    const int boffw = ((jj >> 1) * 8 + iL) * WST + (jj & 1) * 4;         // B lanes

    float af[16];
    uint32_t bhw[4], blw[4];

    auto LOAD = [&](int kc) {
        const float* ap = arow + kc * 32;
        float4 v;
        v = *(const float4*)(ap + 0);  af[0] = v.x;  af[1] = v.y;  af[2] = v.z;  af[3] = v.w;
        v = *(const float4*)(ap + 4);  af[4] = v.x;  af[5] = v.y;  af[6] = v.z;  af[7] = v.w;
        v = *(const float4*)(ap + 8);  af[8] = v.x;  af[9] = v.y;  af[10] = v.z; af[11] = v.w;
        v = *(const float4*)(ap + 12); af[12] = v.x; af[13] = v.y; af[14] = v.z; af[15] = v.w;
        const int off = (kc * 16 + sbw) * 512;
        bhw[0] = bh[off];        bhw[1] = bh[off + 512];
        bhw[2] = bh[off + 1024]; bhw[3] = bh[off + 1536];
        blw[0] = bl[off];        blw[1] = bl[off + 512];
        blw[2] = bl[off + 1024]; blw[3] = bl[off + 1536];
    };

    auto STORE = [&](int bi) {
        uint32_t h[8], l[8];
#pragma unroll
        for (int j = 0; j < 8; j++) {
            h[j] = packbf(af[2 * j], af[2 * j + 1]);
            l[j] = packbf(af[2 * j] - lo_f(h[j]), af[2 * j + 1] - hi_f(h[j]));
        }
        uint32_t* pA = sw + bi * BUFW + sar * WST + saw;
        *(uint4*)pA        = make_uint4(h[0], h[1], h[2], h[3]);
        *(uint4*)(pA + 4)  = make_uint4(h[4], h[5], h[6], h[7]);
        uint32_t* pAl = pA + 2560;
        *(uint4*)pAl       = make_uint4(l[0], l[1], l[2], l[3]);
        *(uint4*)(pAl + 4) = make_uint4(l[4], l[5], l[6], l[7]);
        uint32_t* pB = sw + bi * BUFW + 5120 + (tid & 63) * WST + sbw;
        *(uint4*)pB          = make_uint4(bhw[0], bhw[1], bhw[2], bhw[3]);
        *(uint4*)(pB + 1280) = make_uint4(blw[0], blw[1], blw[2], blw[3]);
    };

    auto COMPUTE = [&](int bi) {
        const uint32_t base = sb + (uint32_t)(bi * BUFW) * 4u;
#pragma unroll
        for (int s = 0; s < 2; s++) {
            const int ws = s * 8;
            uint32_t aH[2][4], aL[2][4];
#pragma unroll
            for (int mf = 0; mf < 2; mf++) {
                const uint32_t wa = base + (uint32_t)(((mo + mf * 16) * WST + ws + aoffw) * 4);
                ldsm4(aH[mf][0], aH[mf][1], aH[mf][2], aH[mf][3], wa);
                ldsm4(aL[mf][0], aL[mf][1], aL[mf][2], aL[mf][3], wa + 2560u * 4u);
            }
#pragma unroll
            for (int p = 0; p < 2; p++) {
                const uint32_t wb = base +
                    (uint32_t)((5120 + (no + p * 16) * WST + ws + boffw) * 4);
                uint32_t h0, h1, h2, h3, l0, l1, l2, l3;
                ldsm4(h0, h1, h2, h3, wb);
                ldsm4(l0, l1, l2, l3, wb + 1280u * 4u);
#pragma unroll
                for (int mf = 0; mf < 2; mf++) {
                    mma16816(acc[mf][2 * p],     aH[mf], h0, h1);
                    mma16816(acc[mf][2 * p],     aH[mf], l0, l1);
                    mma16816(acc[mf][2 * p],     aL[mf], h0, h1);
                    mma16816(acc[mf][2 * p + 1], aH[mf], h2, h3);
                    mma16816(acc[mf][2 * p + 1], aH[mf], l2, l3);
                    mma16816(acc[mf][2 * p + 1], aL[mf], h2, h3);
                }
            }
        }
    };

    LOAD(0);
    STORE(0);
    __syncthreads();
    int cur = 0;
    for (int kc = 0; kc < 16; kc++) {
        if (kc < 15) LOAD(kc + 1);
        COMPUTE(cur);
        if (kc < 15) {
            STORE(cur ^ 1);
            __syncthreads();
            cur ^= 1;
        }
    }
}

// ---------------------------------------------------------------------------
// generic C = A @ B (fp32 out).  grid (n/64, m/128).  Used for XW.
// ---------------------------------------------------------------------------
__global__ __launch_bounds__(256, 2) void hmma_gemm_bb(
    const float* __restrict__ A, const uint32_t* __restrict__ Bh,
    const uint32_t* __restrict__ Bl, float* __restrict__ C)
{
    const int bn = blockIdx.x * 64;
    const int bm = blockIdx.y * 128;
    const int tid = threadIdx.x;
    const float* arow = A + (size_t)(bm + (tid >> 1)) * 512 + (tid & 1) * 16;
    float acc[2][4][4] = {};
    hmma_core_bb(arow, Bh + bn + (tid & 63), Bl + bn + (tid & 63), acc);

    const int lane = tid & 31, wid = tid >> 5;
    const int g = lane >> 2, qi = lane & 3;
    const int mo = (wid >> 1) * 32, no = (wid & 1) * 32;
#pragma unroll
    for (int mf = 0; mf < 2; mf++)
#pragma unroll
        for (int f = 0; f < 4; f++) {
            const int r0  = bm + mo + mf * 16 + g;
            const int col = bn + no + f * 8 + 2 * qi;
            *(float2*)(C + (size_t)r0 * 512 + col) =
                make_float2(acc[mf][f][0], acc[mf][f][1]);
            *(float2*)(C + (size_t)(r0 + 8) * 512 + col) =
                make_float2(acc[mf][f][2], acc[mf][f][3]);
        }
}

// ---------------------------------------------------------------------------
// Mega pass1 step: y < 16 -> pass1 tile; y >= 16 -> ladder tile.
// ---------------------------------------------------------------------------
__global__ __launch_bounds__(256, 2) void mega_step_kernel(
    const uint32_t* __restrict__ Rh, const uint32_t* __restrict__ Rl,
    float* __restrict__ O, int t, float* __restrict__ V0,
    const float* __restrict__ LA,
    const uint32_t* __restrict__ LBh, const uint32_t* __restrict__ LBl,
    float* __restrict__ LCf, uint32_t* __restrict__ LCh, uint32_t* __restrict__ LCl)
{
    const int bn  = blockIdx.x * 64;
    const int tid = threadIdx.x;
    const int lane = tid & 31, wid = tid >> 5;
    const int g = lane >> 2, qi = lane & 3;
    const int mo = (wid >> 1) * 32, no = (wid & 1) * 32;

    if (blockIdx.y < 16) {
        const int bm = blockIdx.y * 128;
        const int srow = bm + (tid >> 1);
        const float* arow = O + ((size_t)(srow & 31) * Tn + (size_t)(srow >> 5) * Lc + (t - 1)) * 512
                            + (tid & 1) * 16;
        float acc[2][4][4] = {};
        hmma_core_bb(arow, Rh + bn + (tid & 63), Rl + bn + (tid & 63), acc);

#pragma unroll
        for (int mf = 0; mf < 2; mf++)
#pragma unroll
            for (int f = 0; f < 4; f++) {
                const int col = bn + no + f * 8 + 2 * qi;
#pragma unroll
                for (int h = 0; h < 2; h++) {
                    const int r = bm + mo + mf * 16 + g + h * 8;
                    float* op = O + ((size_t)(r & 31) * Tn + (size_t)(r >> 5) * Lc + t) * 512 + col;
                    float2 e = *(float2*)op;
                    e.x += acc[mf][f][2 * h];
                    e.y += acc[mf][f][2 * h + 1];
                    *(float2*)op = e;
                    if (t == Lc - 1)
                        *(float2*)(V0 + (size_t)r * 512 + col) = e;
                }
            }
    } else {
        const int y2 = blockIdx.y - 16;
        const int z  = y2 >> 2;
        const int mrow = (y2 & 3) * 128;
        const float* arow = LA + (size_t)z * SZ + (size_t)(mrow + (tid >> 1)) * 512 + (tid & 1) * 16;
        float acc[2][4][4] = {};
        hmma_core_bb(arow, LBh + bn + (tid & 63), LBl + bn + (tid & 63), acc);

        float* Cz = LCf + (size_t)z * SZ;
        uint32_t* Dh = LCh + (size_t)z * SZW;
        uint32_t* Dl = LCl + (size_t)z * SZW;
#pragma unroll
        for (int mf = 0; mf < 2; mf++)
#pragma unroll
            for (int f = 0; f < 4; f++) {
                const int r0  = mrow + mo + mf * 16 + g;
                const int col = bn + no + f * 8 + 2 * qi;
                *(float2*)(Cz + (size_t)r0 * 512 + col) =
                    make_float2(acc[mf][f][0], acc[mf][f][1]);
                *(float2*)(Cz + (size_t)(r0 + 8) * 512 + col) =
                    make_float2(acc[mf][f][2], acc[mf][f][3]);

                float pc0 = __shfl_sync(0xffffffffu, acc[mf][f][0], (lane + 4) & 31);
                float pc1 = __shfl_sync(0xffffffffu, acc[mf][f][1], (lane + 4) & 31);
                float pc2 = __shfl_sync(0xffffffffu, acc[mf][f][2], (lane + 4) & 31);
                float pc3 = __shfl_sync(0xffffffffu, acc[mf][f][3], (lane + 4) & 31);
                if ((g & 1) == 0) {
                    const int w0 = r0 >> 1;
                    const int w1 = (r0 + 8) >> 1;
                    uint32_t h0 = packbf(acc[mf][f][0], pc0);
                    Dh[(size_t)w0 * 512 + col] = h0;
                    Dl[(size_t)w0 * 512 + col] =
                        packbf(acc[mf][f][0] - lo_f(h0), pc0 - hi_f(h0));
                    uint32_t h1 = packbf(acc[mf][f][1], pc1);
                    Dh[(size_t)w0 * 512 + col + 1] = h1;
                    Dl[(size_t)w0 * 512 + col + 1] =
                        packbf(acc[mf][f][1] - lo_f(h1), pc1 - hi_f(h1));
                    uint32_t h2 = packbf(acc[mf][f][2], pc2);
                    Dh[(size_t)w1 * 512 + col] = h2;
                    Dl[(size_t)w1 * 512 + col] =
                        packbf(acc[mf][f][2] - lo_f(h2), pc2 - hi_f(h2));
                    uint32_t h3 = packbf(acc[mf][f][3], pc3);
                    Dh[(size_t)w1 * 512 + col + 1] = h3;
                    Dl[(size_t)w1 * 512 + col + 1] =
                        packbf(acc[mf][f][3] - lo_f(h3), pc3 - hi_f(h3));
                }
            }
    }
}

// ---------------------------------------------------------------------------
// Hillis-Steele scan step: Vout[c] = Vin[c] + (c>=d ? Vin[c-d] @ S^d : 0)
// ---------------------------------------------------------------------------
__global__ __launch_bounds__(256, 2) void hmma_scan_step(
    float* __restrict__ Vout, const float* __restrict__ Vin,
    const uint32_t* __restrict__ Sh, const uint32_t* __restrict__ Sl, int d)
{
    const int bn = blockIdx.x * 64;
    const int bm = blockIdx.y * 128;
    const int tid = threadIdx.x;
    const int srow = bm + (tid >> 1);
    const int csrc = (srow >> 5) - d;
    const int asrc = (csrc >= 0) ? (csrc * 32 + (srow & 31)) : srow;
    const float* arow = Vin + (size_t)asrc * 512 + (tid & 1) * 16;
    float acc[2][4][4] = {};
    hmma_core_bb(arow, Sh + bn + (tid & 63), Sl + bn + (tid & 63), acc);

    const int lane = tid & 31, wid = tid >> 5;
    const int g = lane >> 2, qi = lane & 3;
    const int mo = (wid >> 1) * 32, no = (wid & 1) * 32;
#pragma unroll
    for (int mf = 0; mf < 2; mf++)
#pragma unroll
        for (int f = 0; f < 4; f++) {
            const int col = bn + no + f * 8 + 2 * qi;
#pragma unroll
            for (int h = 0; h < 2; h++) {
                const int r = bm + mo + mf * 16 + g + h * 8;
                float2 e = *(const float2*)(Vin + (size_t)r * 512 + col);
                if ((r >> 5) >= d) {
                    e.x += acc[mf][f][2 * h];
                    e.y += acc[mf][f][2 * h + 1];
                }
                *(float2*)(Vout + (size_t)r * 512 + col) = e;
            }
        }
}

// ---------------------------------------------------------------------------
// pass3: O[b, 16*(c+1)+t, :] += V[c] @ R^{t+1}.  grid (8, 16, 16: t)
// ---------------------------------------------------------------------------
__global__ __launch_bounds__(256, 2) void hmma_pass3_bb(
    float* __restrict__ O, const float* __restrict__ V,
    const uint32_t* __restrict__ Rh, const uint32_t* __restrict__ Rl)
{
    const int t  = blockIdx.z;
    const int bn = blockIdx.x * 64;
    const int bm = blockIdx.y * 128;
    const int tid = threadIdx.x;
    const float* arow = V + (size_t)(bm + (tid >> 1)) * 512 + (tid & 1) * 16;
    float acc[2][4][4] = {};
    hmma_core_bb(arow, Rh + (size_t)t * SZW + bn + (tid & 63),
                 Rl + (size_t)t * SZW + bn + (tid & 63), acc);

    const int lane = tid & 31, wid = tid >> 5;
    const int g = lane >> 2, qi = lane & 3;
    const int mo = (wid >> 1) * 32, no = (wid & 1) * 32;
#pragma unroll
    for (int mf = 0; mf < 2; mf++)
#pragma unroll
        for (int f = 0; f < 4; f++) {
            const int col = bn + no + f * 8 + 2 * qi;
#pragma unroll
            for (int h = 0; h < 2; h++) {
                const int r = bm + mo + mf * 16 + g + h * 8;
                const int cidx = r >> 5;       // = c-1
                if (cidx < Cc - 1) {
                    const int b = r & 31;
                    float* op = O + ((size_t)b * Tn + (size_t)(cidx + 1) * Lc + t) * 512 + col;
                    float2 e = *(float2*)op;
                    e.x += acc[mf][f][2 * h];
                    e.y += acc[mf][f][2 * h + 1];
                    *(float2*)op = e;
                }
            }
        }
}

// ---------------------------------------------------------------------------
// utilities
// ---------------------------------------------------------------------------
__global__ void pack_kernel(const float* __restrict__ src,
                            uint32_t* __restrict__ dh, uint32_t* __restrict__ dl,
                            int total)
{
    const int i = blockIdx.x * 256 + threadIdx.x;
    if (i >= total) return;
    const int w = i >> 9, n = i & 511;
    const float* s = src + (size_t)(2 * w) * 512 + n;
    const float s0 = s[0], s1 = s[512];
    const uint32_t h = packbf(s0, s1);
    dh[i] = h;
    dl[i] = packbf(s0 - lo_f(h), s1 - hi_f(h));
}

__global__ void copy_floats_kernel(float* __restrict__ dst,
                                   const float* __restrict__ src, int n4)
{
    int i = blockIdx.x * blockDim.x + threadIdx.x;
    if (i < n4) ((float4*)dst)[i] = ((const float4*)src)[i];
}

// ---------------------------------------------------------------------------
// Launch sequence
// ---------------------------------------------------------------------------
extern "C" void kernel_launch(void* const* d_in, const int* in_sizes, int n_in,
                              void* d_out, int out_size)
{
    const float* x = (const float*)d_in[0];
    const float* w = (const float*)d_in[1];
    const float* r = (const float*)d_in[2];
    float* o = (float*)d_out;
    (void)in_sizes; (void)n_in; (void)out_size;

    float *Rf, *Sf, *V0, *V1;
    uint32_t *Rh, *Rl, *Sh, *Sl, *Wh, *Wl;
    cudaGetSymbolAddress((void**)&Rf, g_Rf);
    cudaGetSymbolAddress((void**)&Rh, g_Rh);
    cudaGetSymbolAddress((void**)&Rl, g_Rl);
    cudaGetSymbolAddress((void**)&Sf, g_Sf);
    cudaGetSymbolAddress((void**)&Sh, g_Sh);
    cudaGetSymbolAddress((void**)&Sl, g_Sl);
    cudaGetSymbolAddress((void**)&Wh, g_Wh);
    cudaGetSymbolAddress((void**)&Wl, g_Wl);
    cudaGetSymbolAddress((void**)&V0, g_V0);
    cudaGetSymbolAddress((void**)&V1, g_V1);

    cudaFuncSetAttribute(hmma_gemm_bb,     cudaFuncAttributeMaxDynamicSharedMemorySize, SMEM_BYTES);
    cudaFuncSetAttribute(mega_step_kernel, cudaFuncAttributeMaxDynamicSharedMemorySize, SMEM_BYTES);
    cudaFuncSetAttribute(hmma_scan_step,   cudaFuncAttributeMaxDynamicSharedMemorySize, SMEM_BYTES);
    cudaFuncSetAttribute(hmma_pass3_bb,    cudaFuncAttributeMaxDynamicSharedMemorySize, SMEM_BYTES);

    // Prologue: pack W and R, seed Rf slot 0 with R^1.
    pack_kernel<<<SZW / 256, 256>>>(w, Wh, Wl, SZW);
    pack_kernel<<<SZW / 256, 256>>>(r, Rh, Rl, SZW);
    copy_floats_kernel<<<SZ / 4 / 256, 256>>>(Rf, r, SZ / 4);

    // Phase A: O = X @ W
    hmma_gemm_bb<<<dim3(8, M / 128), 256, SMEM_BYTES>>>(x, Wh, Wl, o);

    // Phase C + B: pass1 steps with ladder piggyback.
    struct Lad { const float* A; const uint32_t *Bh, *Bl; float* Cf; uint32_t *Ch, *Cl; int mt; };
    Lad lad[16];
    for (int t = 0; t < 16; t++) lad[t] = {o, Rh, Rl, Rf, Rh, Rl, 0};
    lad[1]  = {r,            Rh,            Rl,            Rf + (size_t)1 * SZ,  Rh + (size_t)1 * SZW,  Rl + (size_t)1 * SZW,  4};   // R^2
    lad[2]  = {Rf,           Rh + 1 * SZW,  Rl + 1 * SZW,  Rf + (size_t)2 * SZ,  Rh + (size_t)2 * SZW,  Rl + (size_t)2 * SZW,  8};   // R^3,R^4
    lad[3]  = {Rf,           Rh + 3 * SZW,  Rl + 3 * SZW,  Rf + (size_t)4 * SZ,  Rh + (size_t)4 * SZW,  Rl + (size_t)4 * SZW,  16};  // R^5..R^8
    lad[4]  = {Rf,           Rh + 7 * SZW,  Rl + 7 * SZW,  Rf + (size_t)8 * SZ,  Rh + (size_t)8 * SZW,  Rl + (size_t)8 * SZW,  32};  // R^9..R^16
    lad[5]  = {Rf + 15 * SZ, Rh + 15 * SZW, Rl + 15 * SZW, Sf,                   Sh,                    Sl,                    4};   // S^2
    lad[6]  = {Sf,           Sh,            Sl,            Sf + (size_t)1 * SZ,  Sh + (size_t)1 * SZW,  Sl + (size_t)1 * SZW,  4};   // S^4
    lad[7]  = {Sf + 1 * SZ,  Sh + 1 * SZW,  Sl + 1 * SZW,  Sf + (size_t)2 * SZ,  Sh + (size_t)2 * SZW,  Sl + (size_t)2 * SZW,  4};   // S^8
    lad[8]  = {Sf + 2 * SZ,  Sh + 2 * SZW,  Sl + 2 * SZW,  Sf + (size_t)3 * SZ,  Sh + (size_t)3 * SZW,  Sl + (size_t)3 * SZW,  4};   // S^16
    lad[9]  = {Sf + 3 * SZ,  Sh + 3 * SZW,  Sl + 3 * SZW,  Sf + (size_t)4 * SZ,  Sh + (size_t)4 * SZW,  Sl + (size_t)4 * SZW,  4};   // S^32

    for (int t = 1; t < Lc; t++) {
        const Lad& L = lad[t];
        mega_step_kernel<<<dim3(8, 16 + L.mt), 256, SMEM_BYTES>>>(
            Rh, Rl, o, t, V0, L.A, L.Bh, L.Bl, L.Cf, L.Ch, L.Cl);
    }

    // Phase D: carry scan (Hillis-Steele over 64 chunk states)
    const float* vin = V0;
    float* vout = V1;
    for (int i = 0; i < 6; i++) {
        const int d = 1 << i;
        const uint32_t* Sph = (i == 0) ? (Rh + (size_t)15 * SZW) : (Sh + (size_t)(i - 1) * SZW);
        const uint32_t* Spl = (i == 0) ? (Rl + (size_t)15 * SZW) : (Sl + (size_t)(i - 1) * SZW);
        hmma_scan_step<<<dim3(8, 16), 256, SMEM_BYTES>>>(vout, vin, Sph, Spl, d);
        const float* tmp = vin; vin = vout; vout = (float*)tmp;
    }

    // Phase E: batched correction
    hmma_pass3_bb<<<dim3(8, 16, 16), 256, SMEM_BYTES>>>(o, vin, Rh, Rl);
}